// round 14
// baseline (speedup 1.0000x reference)
#include <cuda_runtime.h>
#include <cstdint>

// ---------------------------------------------------------------------------
// Fused causal attention head via warp-level tf32 mma.sync. One CTA per batch,
// 2 CTAs/SM. R14: K is never computed -- S = Q*K^T = X*(Wq^T*Wk)*X^T, so a
// tiny pre-kernel computes M^T = (0.125*CMP1) * (Wq^T*Wk)^T once (batch-
// independent), and the main kernel does Y = X*M^T (replacing Q) then
// S = Y*X^T with staged X as the B operand. Deletes the K GEMM, its fragment
// loads and its epilogue entirely. Permuted-k mapping throughout (lane q4
// carries k=2q4,2q4+1): accumulator layout == A-fragment layout. Raw-trunc
// sites: ax frags (bias compensated via CMP1 in M and Wv), P (cancels in
// softmax normalization). Everything SMEM-resident is rounded tf32.
//   x:[4096,128,64] f32, Wq/Wk/Wv:[64,64] f32, out:[4096,128,64] f32
// ---------------------------------------------------------------------------

#define DEVINL __device__ __forceinline__

static constexpr int T = 128;
static constexpr int C = 64;
static constexpr int H = 64;

// mean tf32-truncation bias compensation (one stage): 1 + 2^-11.5
static constexpr float CMP1 = 1.000345f;

static constexpr int RST = 72;    // row stride (words) X / Mt / Wv (72 % 32 == 8)
static constexpr int VST = 136;   // row stride (words) V^T        (136 % 32 == 8)

static constexpr uint32_t SM_X  = 0;                      // X  128x72w = 36864 B
static constexpr uint32_t SM_MT = 36864;                  // Mt  64x72w = 18432 B
static constexpr uint32_t SM_WV = SM_MT + 18432;          // Wv  64x72w = 18432 B
static constexpr uint32_t SM_V  = SM_WV + 18432;          // V^T 64x136w = 34816 B
static constexpr uint32_t SM_TOT = SM_V + 64 * VST * 4;   // 108544 -> 2 CTAs/SM

// Precomputed M^T: Mt[c'][c] = 0.125*CMP1 * sum_h Wq[h][c]*Wk[h][c']
__device__ float g_Mt[64 * 64];

DEVINL uint32_t f2tf(float f) {
    uint32_t r; asm("cvt.rna.tf32.f32 %0, %1;" : "=r"(r) : "f"(f)); return r;
}
DEVINL float ex2f(float x) {
    float y; asm("ex2.approx.ftz.f32 %0, %1;" : "=f"(y) : "f"(x)); return y;
}
DEVINL void sts32(uint32_t a, uint32_t v) {
    asm volatile("st.shared.b32 [%0], %1;" :: "r"(a), "r"(v) : "memory");
}
DEVINL void sts128(uint32_t a, uint32_t r0, uint32_t r1, uint32_t r2, uint32_t r3) {
    asm volatile("st.shared.v4.b32 [%0], {%1,%2,%3,%4};"
                 :: "r"(a), "r"(r0), "r"(r1), "r"(r2), "r"(r3) : "memory");
}
DEVINL uint2 lds64(uint32_t a) {
    uint2 v;
    asm volatile("ld.shared.v2.b32 {%0,%1}, [%2];" : "=r"(v.x), "=r"(v.y) : "r"(a));
    return v;
}

// D += A(16x8) * B(8x8), tf32, fp32 accum.
// Permuted-k convention: frag slot q4 carries k=2q4, slot q4+4 carries k=2q4+1.
DEVINL void mma8(float d[4], const uint32_t a[4], uint32_t b0, uint32_t b1) {
    asm volatile(
        "mma.sync.aligned.m16n8k8.row.col.f32.tf32.tf32.f32 "
        "{%0,%1,%2,%3}, {%4,%5,%6,%7}, {%8,%9}, {%0,%1,%2,%3};"
        : "+f"(d[0]), "+f"(d[1]), "+f"(d[2]), "+f"(d[3])
        : "r"(a[0]), "r"(a[1]), "r"(a[2]), "r"(a[3]), "r"(b0), "r"(b1));
}

// ---- Pre-kernel: M^T = (0.125*CMP1) * (Wq^T Wk)^T, fp32, batch-independent ----
extern "C" __global__ void precompute_mt_kernel(const float* __restrict__ wq,
                                                const float* __restrict__ wk)
{
    int idx = blockIdx.x * 256 + threadIdx.x;   // 0..4095
    int cp = idx >> 6;      // c' = Mt row
    int c  = idx & 63;      // c  = Mt col
    float sum = 0.f;
    #pragma unroll 8
    for (int h = 0; h < 64; h++)
        sum += wq[h * 64 + c] * wk[h * 64 + cp];
    g_Mt[cp * 64 + c] = sum * (0.125f * CMP1);
}

extern "C" __global__ void __launch_bounds__(256, 2)
attn_head_kernel(const float* __restrict__ xg, const float* __restrict__ wvg,
                 float* __restrict__ outg)
{
    extern __shared__ __align__(16) char smc[];
    const uint32_t sm = [&] { uint32_t a;
        asm("{ .reg .u64 t; cvta.to.shared.u64 t, %1; cvt.u32.u64 %0, t; }"
            : "=r"(a) : "l"(smc)); return a; }();
    const int tid  = threadIdx.x;
    const int lane = tid & 31;
    const int w    = tid >> 5;          // warp 0..7
    const int b    = blockIdx.x;
    const int g    = lane >> 2;         // group id 0..7
    const int q4   = lane & 3;          // thread-in-group 0..3
    const int r_lo = 16 * w + g;        // CTA-local rows owned by this lane
    const int r_hi = r_lo + 8;

    // ---- X A-fragments straight from gmem: LDG.64 float2, RAW fp32 bits
    //      (tf32 mma truncates in HW; bias compensated inside M and Wv). ----
    const float2* xb2 = reinterpret_cast<const float2*>(xg + (size_t)b * T * C);
    uint32_t ax[8][4];
    #pragma unroll
    for (int kt = 0; kt < 8; kt++) {
        float2 lo = xb2[r_lo * 32 + kt * 4 + q4];
        float2 hi = xb2[r_hi * 32 + kt * 4 + q4];
        ax[kt][0] = __float_as_uint(lo.x);   // (r_lo, 2q4)
        ax[kt][1] = __float_as_uint(hi.x);   // (r_hi, 2q4)
        ax[kt][2] = __float_as_uint(lo.y);   // (r_lo, 2q4+1)
        ax[kt][3] = __float_as_uint(hi.y);   // (r_hi, 2q4+1)
    }

    // ---- Stage X (rounded tf32; S-phase B operand) ----
    {
        const float4* xp4 = reinterpret_cast<const float4*>(xg + (size_t)b * T * C);
        #pragma unroll
        for (int j = 0; j < 8; j++) {
            int i = tid + j * 256;          // 0..2047 float4
            int row = i >> 4, c4 = i & 15;
            float4 v = xp4[i];
            sts128(sm + SM_X + (row * RST + c4 * 4) * 4,
                   f2tf(v.x), f2tf(v.y), f2tf(v.z), f2tf(v.w));
        }
    }
    // ---- Stage Mt (already scaled in pre-kernel) and Wv (x CMP1) ----
    {
        const float4* mp4 = reinterpret_cast<const float4*>(g_Mt);
        #pragma unroll
        for (int j = 0; j < 4; j++) {
            int i = tid + j * 256;          // 0..1023 float4
            int row = i >> 4, c4 = i & 15;
            float4 v = mp4[i];
            sts128(sm + SM_MT + (row * RST + c4 * 4) * 4,
                   f2tf(v.x), f2tf(v.y), f2tf(v.z), f2tf(v.w));
        }
        const float4* wp4 = reinterpret_cast<const float4*>(wvg);
        #pragma unroll
        for (int j = 0; j < 4; j++) {
            int i = tid + j * 256;
            int row = i >> 4, c4 = i & 15;
            float4 v = wp4[i];
            sts128(sm + SM_WV + (row * RST + c4 * 4) * 4,
                   f2tf(v.x * CMP1), f2tf(v.y * CMP1),
                   f2tf(v.z * CMP1), f2tf(v.w * CMP1));
        }
    }
    __syncthreads();

    // ---- Y = X * M^T -> registers (accumulator layout) ----
    float y[8][4];
    #pragma unroll
    for (int nt = 0; nt < 8; nt++) {
        y[nt][0] = y[nt][1] = y[nt][2] = y[nt][3] = 0.f;
        #pragma unroll
        for (int kt = 0; kt < 8; kt++) {
            uint2 bb = lds64(sm + SM_MT + ((nt * 8 + g) * RST + kt * 8 + 2 * q4) * 4);
            mma8(y[nt], ax[kt], bb.x, bb.y);
        }
    }

    // ---- A-frags of Y: cvt.rna (rounded; ends y[]'s live range) ----
    uint32_t aq[8][4];
    #pragma unroll
    for (int kt = 0; kt < 8; kt++) {
        aq[kt][0] = f2tf(y[kt][0]);   // (r_lo, 2q4)
        aq[kt][1] = f2tf(y[kt][2]);   // (r_hi, 2q4)
        aq[kt][2] = f2tf(y[kt][1]);   // (r_lo, 2q4+1)
        aq[kt][3] = f2tf(y[kt][3]);   // (r_hi, 2q4+1)
    }

    // ---- V = X * Wv^T -> SM_V (V^T row-major) ----
    #pragma unroll
    for (int nt = 0; nt < 8; nt++) {
        float acc[4] = {0.f, 0.f, 0.f, 0.f};
        #pragma unroll
        for (int kt = 0; kt < 8; kt++) {
            uint2 bb = lds64(sm + SM_WV + ((nt * 8 + g) * RST + kt * 8 + 2 * q4) * 4);
            mma8(acc, ax[kt], bb.x, bb.y);
        }
        // V^T[feat][token]: feat = nt*8+2q4 (+1), token = r_lo / r_hi
        uint32_t f0 = sm + SM_V + ((nt * 8 + 2 * q4) * VST) * 4;
        sts32(f0 + r_lo * 4,           f2tf(acc[0]));
        sts32(f0 + (VST + r_lo) * 4,   f2tf(acc[1]));
        sts32(f0 + r_hi * 4,           f2tf(acc[2]));
        sts32(f0 + (VST + r_hi) * 4,   f2tf(acc[3]));
    }

    // ---- Phase 2: S = Y * X^T (B operand = staged X; causal tile skip) ----
    float s[16][4];
    #pragma unroll
    for (int nt = 0; nt < 16; nt++)
        s[nt][0] = s[nt][1] = s[nt][2] = s[nt][3] = 0.f;
    const int tile_max = 2 * w + 2;
    #pragma unroll
    for (int nt = 0; nt < 16; nt++) {
        if (nt < tile_max) {
            #pragma unroll
            for (int kt = 0; kt < 8; kt++) {
                uint2 bb = lds64(sm + SM_X + ((nt * 8 + g) * RST + kt * 8 + 2 * q4) * 4);
                mma8(s[nt], aq[kt], bb.x, bb.y);
            }
        }
    }

    // ---- Causal softmax in registers (row spread over a lane quad) ----
    float m_lo = -1e30f, m_hi = -1e30f;
    #pragma unroll
    for (int nt = 0; nt < 16; nt++) {
        #pragma unroll
        for (int e = 0; e < 2; e++) {
            int col = nt * 8 + 2 * q4 + e;
            if (col <= r_lo) m_lo = fmaxf(m_lo, s[nt][e]);
            if (col <= r_hi) m_hi = fmaxf(m_hi, s[nt][2 + e]);
        }
    }
    m_lo = fmaxf(m_lo, __shfl_xor_sync(~0u, m_lo, 1));
    m_lo = fmaxf(m_lo, __shfl_xor_sync(~0u, m_lo, 2));
    m_hi = fmaxf(m_hi, __shfl_xor_sync(~0u, m_hi, 1));
    m_hi = fmaxf(m_hi, __shfl_xor_sync(~0u, m_hi, 2));

    const float L2E = 1.4426950408889634f;
    float sum_lo = 0.f, sum_hi = 0.f;
    #pragma unroll
    for (int nt = 0; nt < 16; nt++) {
        #pragma unroll
        for (int e = 0; e < 2; e++) {
            int col = nt * 8 + 2 * q4 + e;
            float pl = (col <= r_lo) ? ex2f((s[nt][e]     - m_lo) * L2E) : 0.f;
            float ph = (col <= r_hi) ? ex2f((s[nt][2 + e] - m_hi) * L2E) : 0.f;
            sum_lo += pl; sum_hi += ph;
            s[nt][e]     = pl;   // P raw fp32; truncation bias cancels in the
            s[nt][2 + e] = ph;   // normalization (num and den biased alike)
        }
    }
    sum_lo += __shfl_xor_sync(~0u, sum_lo, 1);
    sum_lo += __shfl_xor_sync(~0u, sum_lo, 2);
    sum_hi += __shfl_xor_sync(~0u, sum_hi, 1);
    sum_hi += __shfl_xor_sync(~0u, sum_hi, 2);
    const float inv_lo = 1.f / sum_lo, inv_hi = 1.f / sum_hi;

    __syncthreads();   // all V^T writes visible before any warp reads SM_V

    // ---- Phase 4: O = P * V. P A-frags = register permutation of s[] ----
    float o[8][4];
    #pragma unroll
    for (int nt = 0; nt < 8; nt++)
        o[nt][0] = o[nt][1] = o[nt][2] = o[nt][3] = 0.f;
    #pragma unroll
    for (int kt = 0; kt < 16; kt++) {
        if (kt < tile_max) {
            uint32_t ap[4];
            ap[0] = __float_as_uint(s[kt][0]);   // (r_lo, token 2q4)
            ap[1] = __float_as_uint(s[kt][2]);   // (r_hi, token 2q4)
            ap[2] = __float_as_uint(s[kt][1]);   // (r_lo, token 2q4+1)
            ap[3] = __float_as_uint(s[kt][3]);   // (r_hi, token 2q4+1)
            #pragma unroll
            for (int nt = 0; nt < 8; nt++) {
                uint2 bb = lds64(sm + SM_V + ((nt * 8 + g) * VST + kt * 8 + 2 * q4) * 4);
                mma8(o[nt], ap, bb.x, bb.y);
            }
        }
    }

    // ---- Normalize and store ----
    float* ob = outg + (size_t)b * T * H;
    #pragma unroll
    for (int nt = 0; nt < 8; nt++) {
        float2 vlo = make_float2(o[nt][0] * inv_lo, o[nt][1] * inv_lo);
        float2 vhi = make_float2(o[nt][2] * inv_hi, o[nt][3] * inv_hi);
        *reinterpret_cast<float2*>(ob + r_lo * 64 + nt * 8 + 2 * q4) = vlo;
        *reinterpret_cast<float2*>(ob + r_hi * 64 + nt * 8 + 2 * q4) = vhi;
    }
}

// ------------------------------ launcher -----------------------------------

extern "C" void kernel_launch(void* const* d_in, const int* in_sizes, int n_in,
                              void* d_out, int out_size) {
    const float* x  = (const float*)d_in[0];
    const float* wq = (const float*)d_in[1];
    const float* wk = (const float*)d_in[2];
    const float* wv = (const float*)d_in[3];
    float* out = (float*)d_out;
    const int nb = in_sizes[0] / (T * C);

    precompute_mt_kernel<<<16, 256>>>(wq, wk);

    cudaFuncSetAttribute(attn_head_kernel,
                         cudaFuncAttributeMaxDynamicSharedMemorySize, (int)SM_TOT);
    attn_head_kernel<<<nb, 256, SM_TOT>>>(x, wv, out);
}

// round 15
// speedup vs baseline: 1.0082x; 1.0082x over previous
#include <cuda_runtime.h>
#include <cstdint>

// ---------------------------------------------------------------------------
// Fused causal attention head via warp-level tf32 mma.sync. One CTA per batch,
// 2 CTAs/SM. K is never computed -- S = Q*K^T = X*(Wq^T*Wk)*X^T: a tiny
// pre-kernel computes M^T = (0.125*CMP1)*(Wq^T*Wk)^T once (R15: fully
// unrolled so all 128 loads per thread are in flight -> ~1us, was ~4-6us),
// and the main kernel does Y = X*M^T then S = Y*X^T with staged X as the B
// operand. Permuted-k mapping (lane q4 carries k=2q4,2q4+1): accumulator
// layout == A-fragment layout. Raw-trunc sites: ax frags (bias compensated
// via CMP1 in M and Wv), P (bias absorbed; measured safe). SMEM-resident
// operands are rounded tf32.
//   x:[4096,128,64] f32, Wq/Wk/Wv:[64,64] f32, out:[4096,128,64] f32
// ---------------------------------------------------------------------------

#define DEVINL __device__ __forceinline__

static constexpr int T = 128;
static constexpr int C = 64;
static constexpr int H = 64;

// mean tf32-truncation bias compensation (one stage): 1 + 2^-11.5
static constexpr float CMP1 = 1.000345f;

static constexpr int RST = 72;    // row stride (words) X / Mt / Wv (72 % 32 == 8)
static constexpr int VST = 136;   // row stride (words) V^T        (136 % 32 == 8)

static constexpr uint32_t SM_X  = 0;                      // X  128x72w = 36864 B
static constexpr uint32_t SM_MT = 36864;                  // Mt  64x72w = 18432 B
static constexpr uint32_t SM_WV = SM_MT + 18432;          // Wv  64x72w = 18432 B
static constexpr uint32_t SM_V  = SM_WV + 18432;          // V^T 64x136w = 34816 B
static constexpr uint32_t SM_TOT = SM_V + 64 * VST * 4;   // 108544 -> 2 CTAs/SM

// Precomputed M^T: Mt[c'][c] = 0.125*CMP1 * sum_h Wq[h][c]*Wk[h][c']
__device__ float g_Mt[64 * 64];

DEVINL uint32_t f2tf(float f) {
    uint32_t r; asm("cvt.rna.tf32.f32 %0, %1;" : "=r"(r) : "f"(f)); return r;
}
DEVINL float ex2f(float x) {
    float y; asm("ex2.approx.ftz.f32 %0, %1;" : "=f"(y) : "f"(x)); return y;
}
DEVINL void sts32(uint32_t a, uint32_t v) {
    asm volatile("st.shared.b32 [%0], %1;" :: "r"(a), "r"(v) : "memory");
}
DEVINL void sts128(uint32_t a, uint32_t r0, uint32_t r1, uint32_t r2, uint32_t r3) {
    asm volatile("st.shared.v4.b32 [%0], {%1,%2,%3,%4};"
                 :: "r"(a), "r"(r0), "r"(r1), "r"(r2), "r"(r3) : "memory");
}
DEVINL uint2 lds64(uint32_t a) {
    uint2 v;
    asm volatile("ld.shared.v2.b32 {%0,%1}, [%2];" : "=r"(v.x), "=r"(v.y) : "r"(a));
    return v;
}

// D += A(16x8) * B(8x8), tf32, fp32 accum.
// Permuted-k convention: frag slot q4 carries k=2q4, slot q4+4 carries k=2q4+1.
DEVINL void mma8(float d[4], const uint32_t a[4], uint32_t b0, uint32_t b1) {
    asm volatile(
        "mma.sync.aligned.m16n8k8.row.col.f32.tf32.tf32.f32 "
        "{%0,%1,%2,%3}, {%4,%5,%6,%7}, {%8,%9}, {%0,%1,%2,%3};"
        : "+f"(d[0]), "+f"(d[1]), "+f"(d[2]), "+f"(d[3])
        : "r"(a[0]), "r"(a[1]), "r"(a[2]), "r"(a[3]), "r"(b0), "r"(b1));
}

// ---- Pre-kernel: M^T = (0.125*CMP1) * (Wq^T Wk)^T, fp32, batch-independent.
//      Fully unrolled: 128 independent loads per thread (wq coalesced across
//      c, wk broadcast across the warp) -> one-two DRAM round trips total. ----
extern "C" __global__ void precompute_mt_kernel(const float* __restrict__ wq,
                                                const float* __restrict__ wk)
{
    int idx = blockIdx.x * 256 + threadIdx.x;   // 0..4095
    int cp = idx >> 6;      // c' = Mt row
    int c  = idx & 63;      // c  = Mt col
    float a[64], bvals[64];
    #pragma unroll
    for (int h = 0; h < 64; h++) a[h] = wq[h * 64 + c];
    #pragma unroll
    for (int h = 0; h < 64; h++) bvals[h] = wk[h * 64 + cp];
    float sum = 0.f;
    #pragma unroll
    for (int h = 0; h < 64; h++) sum += a[h] * bvals[h];
    g_Mt[cp * 64 + c] = sum * (0.125f * CMP1);
}

extern "C" __global__ void __launch_bounds__(256, 2)
attn_head_kernel(const float* __restrict__ xg, const float* __restrict__ wvg,
                 float* __restrict__ outg)
{
    extern __shared__ __align__(16) char smc[];
    const uint32_t sm = [&] { uint32_t a;
        asm("{ .reg .u64 t; cvta.to.shared.u64 t, %1; cvt.u32.u64 %0, t; }"
            : "=r"(a) : "l"(smc)); return a; }();
    const int tid  = threadIdx.x;
    const int lane = tid & 31;
    const int w    = tid >> 5;          // warp 0..7
    const int b    = blockIdx.x;
    const int g    = lane >> 2;         // group id 0..7
    const int q4   = lane & 3;          // thread-in-group 0..3
    const int r_lo = 16 * w + g;        // CTA-local rows owned by this lane
    const int r_hi = r_lo + 8;

    // ---- X A-fragments straight from gmem: LDG.64 float2, RAW fp32 bits
    //      (tf32 mma truncates in HW; bias compensated inside M and Wv). ----
    const float2* xb2 = reinterpret_cast<const float2*>(xg + (size_t)b * T * C);
    uint32_t ax[8][4];
    #pragma unroll
    for (int kt = 0; kt < 8; kt++) {
        float2 lo = xb2[r_lo * 32 + kt * 4 + q4];
        float2 hi = xb2[r_hi * 32 + kt * 4 + q4];
        ax[kt][0] = __float_as_uint(lo.x);   // (r_lo, 2q4)
        ax[kt][1] = __float_as_uint(hi.x);   // (r_hi, 2q4)
        ax[kt][2] = __float_as_uint(lo.y);   // (r_lo, 2q4+1)
        ax[kt][3] = __float_as_uint(hi.y);   // (r_hi, 2q4+1)
    }

    // ---- Stage X (rounded tf32; S-phase B operand) ----
    {
        const float4* xp4 = reinterpret_cast<const float4*>(xg + (size_t)b * T * C);
        #pragma unroll
        for (int j = 0; j < 8; j++) {
            int i = tid + j * 256;          // 0..2047 float4
            int row = i >> 4, c4 = i & 15;
            float4 v = xp4[i];
            sts128(sm + SM_X + (row * RST + c4 * 4) * 4,
                   f2tf(v.x), f2tf(v.y), f2tf(v.z), f2tf(v.w));
        }
    }
    // ---- Stage Mt (already scaled in pre-kernel) and Wv (x CMP1) ----
    {
        const float4* mp4 = reinterpret_cast<const float4*>(g_Mt);
        #pragma unroll
        for (int j = 0; j < 4; j++) {
            int i = tid + j * 256;          // 0..1023 float4
            int row = i >> 4, c4 = i & 15;
            float4 v = mp4[i];
            sts128(sm + SM_MT + (row * RST + c4 * 4) * 4,
                   f2tf(v.x), f2tf(v.y), f2tf(v.z), f2tf(v.w));
        }
        const float4* wp4 = reinterpret_cast<const float4*>(wvg);
        #pragma unroll
        for (int j = 0; j < 4; j++) {
            int i = tid + j * 256;
            int row = i >> 4, c4 = i & 15;
            float4 v = wp4[i];
            sts128(sm + SM_WV + (row * RST + c4 * 4) * 4,
                   f2tf(v.x * CMP1), f2tf(v.y * CMP1),
                   f2tf(v.z * CMP1), f2tf(v.w * CMP1));
        }
    }
    __syncthreads();

    // ---- Y = X * M^T -> registers (accumulator layout) ----
    float y[8][4];
    #pragma unroll
    for (int nt = 0; nt < 8; nt++) {
        y[nt][0] = y[nt][1] = y[nt][2] = y[nt][3] = 0.f;
        #pragma unroll
        for (int kt = 0; kt < 8; kt++) {
            uint2 bb = lds64(sm + SM_MT + ((nt * 8 + g) * RST + kt * 8 + 2 * q4) * 4);
            mma8(y[nt], ax[kt], bb.x, bb.y);
        }
    }

    // ---- A-frags of Y: cvt.rna (rounded; ends y[]'s live range) ----
    uint32_t aq[8][4];
    #pragma unroll
    for (int kt = 0; kt < 8; kt++) {
        aq[kt][0] = f2tf(y[kt][0]);   // (r_lo, 2q4)
        aq[kt][1] = f2tf(y[kt][2]);   // (r_hi, 2q4)
        aq[kt][2] = f2tf(y[kt][1]);   // (r_lo, 2q4+1)
        aq[kt][3] = f2tf(y[kt][3]);   // (r_hi, 2q4+1)
    }

    // ---- V = X * Wv^T -> SM_V (V^T row-major) ----
    #pragma unroll
    for (int nt = 0; nt < 8; nt++) {
        float acc[4] = {0.f, 0.f, 0.f, 0.f};
        #pragma unroll
        for (int kt = 0; kt < 8; kt++) {
            uint2 bb = lds64(sm + SM_WV + ((nt * 8 + g) * RST + kt * 8 + 2 * q4) * 4);
            mma8(acc, ax[kt], bb.x, bb.y);
        }
        // V^T[feat][token]: feat = nt*8+2q4 (+1), token = r_lo / r_hi
        uint32_t f0 = sm + SM_V + ((nt * 8 + 2 * q4) * VST) * 4;
        sts32(f0 + r_lo * 4,           f2tf(acc[0]));
        sts32(f0 + (VST + r_lo) * 4,   f2tf(acc[1]));
        sts32(f0 + r_hi * 4,           f2tf(acc[2]));
        sts32(f0 + (VST + r_hi) * 4,   f2tf(acc[3]));
    }

    // ---- Phase 2: S = Y * X^T (B operand = staged X; causal tile skip) ----
    float s[16][4];
    #pragma unroll
    for (int nt = 0; nt < 16; nt++)
        s[nt][0] = s[nt][1] = s[nt][2] = s[nt][3] = 0.f;
    const int tile_max = 2 * w + 2;
    #pragma unroll
    for (int nt = 0; nt < 16; nt++) {
        if (nt < tile_max) {
            #pragma unroll
            for (int kt = 0; kt < 8; kt++) {
                uint2 bb = lds64(sm + SM_X + ((nt * 8 + g) * RST + kt * 8 + 2 * q4) * 4);
                mma8(s[nt], aq[kt], bb.x, bb.y);
            }
        }
    }

    // ---- Causal softmax in registers (row spread over a lane quad) ----
    float m_lo = -1e30f, m_hi = -1e30f;
    #pragma unroll
    for (int nt = 0; nt < 16; nt++) {
        #pragma unroll
        for (int e = 0; e < 2; e++) {
            int col = nt * 8 + 2 * q4 + e;
            if (col <= r_lo) m_lo = fmaxf(m_lo, s[nt][e]);
            if (col <= r_hi) m_hi = fmaxf(m_hi, s[nt][2 + e]);
        }
    }
    m_lo = fmaxf(m_lo, __shfl_xor_sync(~0u, m_lo, 1));
    m_lo = fmaxf(m_lo, __shfl_xor_sync(~0u, m_lo, 2));
    m_hi = fmaxf(m_hi, __shfl_xor_sync(~0u, m_hi, 1));
    m_hi = fmaxf(m_hi, __shfl_xor_sync(~0u, m_hi, 2));

    const float L2E = 1.4426950408889634f;
    float sum_lo = 0.f, sum_hi = 0.f;
    #pragma unroll
    for (int nt = 0; nt < 16; nt++) {
        #pragma unroll
        for (int e = 0; e < 2; e++) {
            int col = nt * 8 + 2 * q4 + e;
            float pl = (col <= r_lo) ? ex2f((s[nt][e]     - m_lo) * L2E) : 0.f;
            float ph = (col <= r_hi) ? ex2f((s[nt][2 + e] - m_hi) * L2E) : 0.f;
            sum_lo += pl; sum_hi += ph;
            s[nt][e]     = pl;   // P raw fp32; HW truncates at the PV mma
            s[nt][2 + e] = ph;
        }
    }
    sum_lo += __shfl_xor_sync(~0u, sum_lo, 1);
    sum_lo += __shfl_xor_sync(~0u, sum_lo, 2);
    sum_hi += __shfl_xor_sync(~0u, sum_hi, 1);
    sum_hi += __shfl_xor_sync(~0u, sum_hi, 2);
    const float inv_lo = 1.f / sum_lo, inv_hi = 1.f / sum_hi;

    __syncthreads();   // all V^T writes visible before any warp reads SM_V

    // ---- Phase 4: O = P * V. P A-frags = register permutation of s[] ----
    float o[8][4];
    #pragma unroll
    for (int nt = 0; nt < 8; nt++)
        o[nt][0] = o[nt][1] = o[nt][2] = o[nt][3] = 0.f;
    #pragma unroll
    for (int kt = 0; kt < 16; kt++) {
        if (kt < tile_max) {
            uint32_t ap[4];
            ap[0] = __float_as_uint(s[kt][0]);   // (r_lo, token 2q4)
            ap[1] = __float_as_uint(s[kt][2]);   // (r_hi, token 2q4)
            ap[2] = __float_as_uint(s[kt][1]);   // (r_lo, token 2q4+1)
            ap[3] = __float_as_uint(s[kt][3]);   // (r_hi, token 2q4+1)
            #pragma unroll
            for (int nt = 0; nt < 8; nt++) {
                uint2 bb = lds64(sm + SM_V + ((nt * 8 + g) * VST + kt * 8 + 2 * q4) * 4);
                mma8(o[nt], ap, bb.x, bb.y);
            }
        }
    }

    // ---- Normalize and store ----
    float* ob = outg + (size_t)b * T * H;
    #pragma unroll
    for (int nt = 0; nt < 8; nt++) {
        float2 vlo = make_float2(o[nt][0] * inv_lo, o[nt][1] * inv_lo);
        float2 vhi = make_float2(o[nt][2] * inv_hi, o[nt][3] * inv_hi);
        *reinterpret_cast<float2*>(ob + r_lo * 64 + nt * 8 + 2 * q4) = vlo;
        *reinterpret_cast<float2*>(ob + r_hi * 64 + nt * 8 + 2 * q4) = vhi;
    }
}

// ------------------------------ launcher -----------------------------------

extern "C" void kernel_launch(void* const* d_in, const int* in_sizes, int n_in,
                              void* d_out, int out_size) {
    const float* x  = (const float*)d_in[0];
    const float* wq = (const float*)d_in[1];
    const float* wk = (const float*)d_in[2];
    const float* wv = (const float*)d_in[3];
    float* out = (float*)d_out;
    const int nb = in_sizes[0] / (T * C);

    precompute_mt_kernel<<<16, 256>>>(wq, wk);

    cudaFuncSetAttribute(attn_head_kernel,
                         cudaFuncAttributeMaxDynamicSharedMemorySize, (int)SM_TOT);
    attn_head_kernel<<<nb, 256, SM_TOT>>>(x, wv, out);
}

// round 16
// speedup vs baseline: 1.0716x; 1.0629x over previous
#include <cuda_runtime.h>
#include <cstdint>

// ---------------------------------------------------------------------------
// Fused causal attention head via warp-level tf32 mma.sync. One CTA per batch,
// 2 CTAs/SM. K never computed: S = X*(Wq^T*Wk)*X^T; pre-kernel computes
// M^T = (0.125*CMP1^3)*(Wq^T*Wk)^T once. R16: ALL staging (X, Mt, Wv) is raw
// fp32 via cp.async (zero cvts; HW tf32 truncation at the mma, bias
// compensated in the Mt scale and in inv*CMP1^3); V epilogue stores raw
// accumulator bits; barrier moved before S so the causally-imbalanced
// S+softmax+PV stretch runs barrier-free. Permuted-k mapping throughout.
//   x:[4096,128,64] f32, Wq/Wk/Wv:[64,64] f32, out:[4096,128,64] f32
// ---------------------------------------------------------------------------

#define DEVINL __device__ __forceinline__

static constexpr int T = 128;
static constexpr int C = 64;
static constexpr int H = 64;

// mean tf32-truncation bias compensation (one stage): 1 + 2^-11.5
static constexpr float CMP1 = 1.000345f;
static constexpr float CMP3 = CMP1 * CMP1 * CMP1;

static constexpr int RST = 72;    // row stride (words) X / Mt / Wv (72 % 32 == 8)
static constexpr int VST = 136;   // row stride (words) V^T        (136 % 32 == 8)

static constexpr uint32_t SM_X  = 0;                      // X  128x72w = 36864 B
static constexpr uint32_t SM_MT = 36864;                  // Mt  64x72w = 18432 B
static constexpr uint32_t SM_WV = SM_MT + 18432;          // Wv  64x72w = 18432 B
static constexpr uint32_t SM_V  = SM_WV + 18432;          // V^T 64x136w = 34816 B
static constexpr uint32_t SM_TOT = SM_V + 64 * VST * 4;   // 108544 -> 2 CTAs/SM

// Precomputed M^T: Mt[c'][c] = 0.125*CMP1^3 * sum_h Wq[h][c]*Wk[h][c']
__device__ float g_Mt[64 * 64];

DEVINL float ex2f(float x) {
    float y; asm("ex2.approx.ftz.f32 %0, %1;" : "=f"(y) : "f"(x)); return y;
}
DEVINL void sts32(uint32_t a, uint32_t v) {
    asm volatile("st.shared.b32 [%0], %1;" :: "r"(a), "r"(v) : "memory");
}
DEVINL uint32_t f2tf(float f) {
    uint32_t r; asm("cvt.rna.tf32.f32 %0, %1;" : "=r"(r) : "f"(f)); return r;
}
DEVINL uint2 lds64(uint32_t a) {
    uint2 v;
    asm volatile("ld.shared.v2.b32 {%0,%1}, [%2];" : "=r"(v.x), "=r"(v.y) : "r"(a));
    return v;
}
DEVINL void cpasync16(uint32_t saddr, const void* gptr) {
    asm volatile("cp.async.ca.shared.global [%0], [%1], 16;"
                 :: "r"(saddr), "l"(__cvta_generic_to_global(gptr)) : "memory");
}
DEVINL void cpasync_wait_all() {
    asm volatile("cp.async.commit_group;" ::: "memory");
    asm volatile("cp.async.wait_group 0;" ::: "memory");
}

// D += A(16x8) * B(8x8), tf32, fp32 accum.
// Permuted-k convention: frag slot q4 carries k=2q4, slot q4+4 carries k=2q4+1.
DEVINL void mma8(float d[4], const uint32_t a[4], uint32_t b0, uint32_t b1) {
    asm volatile(
        "mma.sync.aligned.m16n8k8.row.col.f32.tf32.tf32.f32 "
        "{%0,%1,%2,%3}, {%4,%5,%6,%7}, {%8,%9}, {%0,%1,%2,%3};"
        : "+f"(d[0]), "+f"(d[1]), "+f"(d[2]), "+f"(d[3])
        : "r"(a[0]), "r"(a[1]), "r"(a[2]), "r"(a[3]), "r"(b0), "r"(b1));
}

// ---- Pre-kernel: M^T = (0.125*CMP1^3) * (Wq^T Wk)^T, fp32. Fully unrolled:
//      all 128 loads per thread in flight. ----
extern "C" __global__ void precompute_mt_kernel(const float* __restrict__ wq,
                                                const float* __restrict__ wk)
{
    int idx = blockIdx.x * 256 + threadIdx.x;   // 0..4095
    int cp = idx >> 6;      // c' = Mt row
    int c  = idx & 63;      // c  = Mt col
    float a[64], bvals[64];
    #pragma unroll
    for (int h = 0; h < 64; h++) a[h] = wq[h * 64 + c];
    #pragma unroll
    for (int h = 0; h < 64; h++) bvals[h] = wk[h * 64 + cp];
    float sum = 0.f;
    #pragma unroll
    for (int h = 0; h < 64; h++) sum += a[h] * bvals[h];
    g_Mt[cp * 64 + c] = sum * (0.125f * CMP3);
}

extern "C" __global__ void __launch_bounds__(256, 2)
attn_head_kernel(const float* __restrict__ xg, const float* __restrict__ wvg,
                 float* __restrict__ outg)
{
    extern __shared__ __align__(16) char smc[];
    const uint32_t sm = [&] { uint32_t a;
        asm("{ .reg .u64 t; cvta.to.shared.u64 t, %1; cvt.u32.u64 %0, t; }"
            : "=r"(a) : "l"(smc)); return a; }();
    const int tid  = threadIdx.x;
    const int lane = tid & 31;
    const int w    = tid >> 5;          // warp 0..7
    const int b    = blockIdx.x;
    const int g    = lane >> 2;         // group id 0..7
    const int q4   = lane & 3;          // thread-in-group 0..3
    const int r_lo = 16 * w + g;        // CTA-local rows owned by this lane
    const int r_hi = r_lo + 8;

    // ---- Stage X / Mt / Wv raw fp32 via cp.async (no cvt, no registers) ----
    {
        const float4* xp4 = reinterpret_cast<const float4*>(xg + (size_t)b * T * C);
        #pragma unroll
        for (int j = 0; j < 8; j++) {
            int i = tid + j * 256;          // 0..2047 float4
            int row = i >> 4, c4 = i & 15;
            cpasync16(sm + SM_X + (row * RST + c4 * 4) * 4, xp4 + i);
        }
        const float4* mp4 = reinterpret_cast<const float4*>(g_Mt);
        const float4* wp4 = reinterpret_cast<const float4*>(wvg);
        #pragma unroll
        for (int j = 0; j < 4; j++) {
            int i = tid + j * 256;          // 0..1023 float4
            int row = i >> 4, c4 = i & 15;
            cpasync16(sm + SM_MT + (row * RST + c4 * 4) * 4, mp4 + i);
            cpasync16(sm + SM_WV + (row * RST + c4 * 4) * 4, wp4 + i);
        }
    }

    // ---- X A-fragments straight from gmem: LDG.64 float2, RAW fp32 bits ----
    const float2* xb2 = reinterpret_cast<const float2*>(xg + (size_t)b * T * C);
    uint32_t ax[8][4];
    #pragma unroll
    for (int kt = 0; kt < 8; kt++) {
        float2 lo = xb2[r_lo * 32 + kt * 4 + q4];
        float2 hi = xb2[r_hi * 32 + kt * 4 + q4];
        ax[kt][0] = __float_as_uint(lo.x);   // (r_lo, 2q4)
        ax[kt][1] = __float_as_uint(hi.x);   // (r_hi, 2q4)
        ax[kt][2] = __float_as_uint(lo.y);   // (r_lo, 2q4+1)
        ax[kt][3] = __float_as_uint(hi.y);   // (r_hi, 2q4+1)
    }

    cpasync_wait_all();
    __syncthreads();

    // ---- V = X * Wv^T -> SM_V (V^T row-major, RAW accumulator bits;
    //      truncation compensated via inv * CMP1^3) ----
    #pragma unroll
    for (int nt = 0; nt < 8; nt++) {
        float acc[4] = {0.f, 0.f, 0.f, 0.f};
        #pragma unroll
        for (int kt = 0; kt < 8; kt++) {
            uint2 bb = lds64(sm + SM_WV + ((nt * 8 + g) * RST + kt * 8 + 2 * q4) * 4);
            mma8(acc, ax[kt], bb.x, bb.y);
        }
        // V^T[feat][token]: feat = nt*8+2q4 (+1), token = r_lo / r_hi
        uint32_t f0 = sm + SM_V + ((nt * 8 + 2 * q4) * VST) * 4;
        sts32(f0 + r_lo * 4,           __float_as_uint(acc[0]));
        sts32(f0 + (VST + r_lo) * 4,   __float_as_uint(acc[1]));
        sts32(f0 + r_hi * 4,           __float_as_uint(acc[2]));
        sts32(f0 + (VST + r_hi) * 4,   __float_as_uint(acc[3]));
    }
    __syncthreads();   // V^T visible; everything after runs barrier-free

    // ---- Y = X * M^T -> registers (accumulator layout) ----
    float y[8][4];
    #pragma unroll
    for (int nt = 0; nt < 8; nt++) {
        y[nt][0] = y[nt][1] = y[nt][2] = y[nt][3] = 0.f;
        #pragma unroll
        for (int kt = 0; kt < 8; kt++) {
            uint2 bb = lds64(sm + SM_MT + ((nt * 8 + g) * RST + kt * 8 + 2 * q4) * 4);
            mma8(y[nt], ax[kt], bb.x, bb.y);
        }
    }

    // ---- A-frags of Y: cvt.rna (rounded; ends y[]'s live range) ----
    uint32_t aq[8][4];
    #pragma unroll
    for (int kt = 0; kt < 8; kt++) {
        aq[kt][0] = f2tf(y[kt][0]);   // (r_lo, 2q4)
        aq[kt][1] = f2tf(y[kt][2]);   // (r_hi, 2q4)
        aq[kt][2] = f2tf(y[kt][1]);   // (r_lo, 2q4+1)
        aq[kt][3] = f2tf(y[kt][3]);   // (r_hi, 2q4+1)
    }

    // ---- Phase 2: S = Y * X^T (B operand = staged raw X; causal tile skip) ----
    float s[16][4];
    #pragma unroll
    for (int nt = 0; nt < 16; nt++)
        s[nt][0] = s[nt][1] = s[nt][2] = s[nt][3] = 0.f;
    const int tile_max = 2 * w + 2;
    #pragma unroll
    for (int nt = 0; nt < 16; nt++) {
        if (nt < tile_max) {
            #pragma unroll
            for (int kt = 0; kt < 8; kt++) {
                uint2 bb = lds64(sm + SM_X + ((nt * 8 + g) * RST + kt * 8 + 2 * q4) * 4);
                mma8(s[nt], aq[kt], bb.x, bb.y);
            }
        }
    }

    // ---- Causal softmax in registers (row spread over a lane quad) ----
    float m_lo = -1e30f, m_hi = -1e30f;
    #pragma unroll
    for (int nt = 0; nt < 16; nt++) {
        #pragma unroll
        for (int e = 0; e < 2; e++) {
            int col = nt * 8 + 2 * q4 + e;
            if (col <= r_lo) m_lo = fmaxf(m_lo, s[nt][e]);
            if (col <= r_hi) m_hi = fmaxf(m_hi, s[nt][2 + e]);
        }
    }
    m_lo = fmaxf(m_lo, __shfl_xor_sync(~0u, m_lo, 1));
    m_lo = fmaxf(m_lo, __shfl_xor_sync(~0u, m_lo, 2));
    m_hi = fmaxf(m_hi, __shfl_xor_sync(~0u, m_hi, 1));
    m_hi = fmaxf(m_hi, __shfl_xor_sync(~0u, m_hi, 2));

    const float L2E = 1.4426950408889634f;
    float sum_lo = 0.f, sum_hi = 0.f;
    #pragma unroll
    for (int nt = 0; nt < 16; nt++) {
        #pragma unroll
        for (int e = 0; e < 2; e++) {
            int col = nt * 8 + 2 * q4 + e;
            float pl = (col <= r_lo) ? ex2f((s[nt][e]     - m_lo) * L2E) : 0.f;
            float ph = (col <= r_hi) ? ex2f((s[nt][2 + e] - m_hi) * L2E) : 0.f;
            sum_lo += pl; sum_hi += ph;
            s[nt][e]     = pl;   // P raw fp32; HW truncates at the PV mma
            s[nt][2 + e] = ph;
        }
    }
    sum_lo += __shfl_xor_sync(~0u, sum_lo, 1);
    sum_lo += __shfl_xor_sync(~0u, sum_lo, 2);
    sum_hi += __shfl_xor_sync(~0u, sum_hi, 1);
    sum_hi += __shfl_xor_sync(~0u, sum_hi, 2);
    // CMP1^3 compensates the V path's three raw-truncation stages
    const float inv_lo = CMP3 / sum_lo, inv_hi = CMP3 / sum_hi;

    // ---- Phase 4: O = P * V. P A-frags = register permutation of s[] ----
    float o[8][4];
    #pragma unroll
    for (int nt = 0; nt < 8; nt++)
        o[nt][0] = o[nt][1] = o[nt][2] = o[nt][3] = 0.f;
    #pragma unroll
    for (int kt = 0; kt < 16; kt++) {
        if (kt < tile_max) {
            uint32_t ap[4];
            ap[0] = __float_as_uint(s[kt][0]);   // (r_lo, token 2q4)
            ap[1] = __float_as_uint(s[kt][2]);   // (r_hi, token 2q4)
            ap[2] = __float_as_uint(s[kt][1]);   // (r_lo, token 2q4+1)
            ap[3] = __float_as_uint(s[kt][3]);   // (r_hi, token 2q4+1)
            #pragma unroll
            for (int nt = 0; nt < 8; nt++) {
                uint2 bb = lds64(sm + SM_V + ((nt * 8 + g) * VST + kt * 8 + 2 * q4) * 4);
                mma8(o[nt], ap, bb.x, bb.y);
            }
        }
    }

    // ---- Normalize and store ----
    float* ob = outg + (size_t)b * T * H;
    #pragma unroll
    for (int nt = 0; nt < 8; nt++) {
        float2 vlo = make_float2(o[nt][0] * inv_lo, o[nt][1] * inv_lo);
        float2 vhi = make_float2(o[nt][2] * inv_hi, o[nt][3] * inv_hi);
        *reinterpret_cast<float2*>(ob + r_lo * 64 + nt * 8 + 2 * q4) = vlo;
        *reinterpret_cast<float2*>(ob + r_hi * 64 + nt * 8 + 2 * q4) = vhi;
    }
}

// ------------------------------ launcher -----------------------------------

extern "C" void kernel_launch(void* const* d_in, const int* in_sizes, int n_in,
                              void* d_out, int out_size) {
    const float* x  = (const float*)d_in[0];
    const float* wq = (const float*)d_in[1];
    const float* wk = (const float*)d_in[2];
    const float* wv = (const float*)d_in[3];
    float* out = (float*)d_out;
    const int nb = in_sizes[0] / (T * C);

    precompute_mt_kernel<<<16, 256>>>(wq, wk);

    cudaFuncSetAttribute(attn_head_kernel,
                         cudaFuncAttributeMaxDynamicSharedMemorySize, (int)SM_TOT);
    attn_head_kernel<<<nb, 256, SM_TOT>>>(x, wv, out);
}